// round 16
// baseline (speedup 1.0000x reference)
#include <cuda_runtime.h>

// Problem shape (fixed by the dataset)
#define BB 4
#define SS 256
#define EE 256
#define MM (BB * SS)

// Scratch: pi[m,f] and (pj[m,f] + b[f]) — 1 MB each
__device__ float g_pi [MM * EE];
__device__ float g_pjb[MM * EE];

// ---------------------------------------------------------------------------
// Kernel 1: per-batch dual GEMM, small CTAs for low latency.
// Per launch: one batch b (256 m-rows). BM=16, BN=32 -> 16 x 8 = 128 CTAs.
// 128 threads, full K=256 resident in SMEM (~90KB), W cols XOR-swizzled,
// packed fma.rn.f32x2, sync-free mainloop (single barrier).
// ---------------------------------------------------------------------------
#define BM 16
#define BN 32

#define XSTR 260     // s_x row stride (floats): 1040B = 65*16
#define WSTR 36      // s_w row stride (floats): 144B  =  9*16

#define SX_FLOATS (BM * XSTR)           //  4160
#define SW_FLOATS (EE * WSTR)           //  9216 per matrix
#define SMEM_BYTES ((SX_FLOATS + 2 * SW_FLOATS) * 4)   // 90,368 B

__device__ __forceinline__ void fma2(unsigned long long& acc,
                                     unsigned long long a,
                                     unsigned long long b)
{
    asm("fma.rn.f32x2 %0, %1, %2, %0;" : "+l"(acc) : "l"(a), "l"(b));
}

__device__ __forceinline__ unsigned long long bcast2(float a)
{
    unsigned long long r;
    asm("mov.b64 %0, {%1, %1};" : "=l"(r) : "r"(__float_as_int(a)));
    return r;
}

__global__ __launch_bounds__(128)
void gemm_kernel(const float* __restrict__ x,
                 const float* __restrict__ W,
                 const float* __restrict__ bias,
                 int mbase)
{
    extern __shared__ float sm[];
    float* s_x  = sm;                          // [BM][XSTR]
    float* s_w1 = sm + SX_FLOATS;              // [256 k][WSTR], swizzled cols
    float* s_w2 = sm + SX_FLOATS + SW_FLOATS;

    const int m0  = mbase + blockIdx.x * BM;
    const int f0  = blockIdx.y * BN;
    const int tid = threadIdx.x;

    const int my  = tid >> 3;    // 0..15: m-row
    const int tx  = tid & 7;     // 0..7 : f-quad (4 floats)

    // ---------------- load x tile [16][256], coalesced ----------------------
    #pragma unroll
    for (int i = 0; i < 8; ++i) {
        int idx = tid + i * 128;              // 0..1023
        int row = idx >> 6;                   // m 0..15
        int c4  = idx & 63;                   // k-float4
        *(float4*)&s_x[row * XSTR + c4 * 4] =
            *(const float4*)&x[(size_t)(m0 + row) * EE + c4 * 4];
    }

    // ---------------- W load: 4x4 register transpose -> [k][f], swizzled ----
    // element W[k][c] stored at col c ^ (k & 28).
    #pragma unroll
    for (int i = 0; i < 4; ++i) {
        int t4 = tid + i * 128;               // 0..511
        int fg = t4 >> 6;                     // f-group 0..7
        int kg = t4 & 63;                     // k-group 0..63
        const float* wb = W + (size_t)(f0 + fg * 4) * (2 * EE) + kg * 4;
        const int csw = (fg * 4) ^ ((kg & 7) << 2);

        float4 a0 = *(const float4*)(wb + 0 * (2 * EE));
        float4 a1 = *(const float4*)(wb + 1 * (2 * EE));
        float4 a2 = *(const float4*)(wb + 2 * (2 * EE));
        float4 a3 = *(const float4*)(wb + 3 * (2 * EE));
        float* d1 = s_w1 + (kg * 4) * WSTR + csw;
        *(float4*)(d1 + 0 * WSTR) = make_float4(a0.x, a1.x, a2.x, a3.x);
        *(float4*)(d1 + 1 * WSTR) = make_float4(a0.y, a1.y, a2.y, a3.y);
        *(float4*)(d1 + 2 * WSTR) = make_float4(a0.z, a1.z, a2.z, a3.z);
        *(float4*)(d1 + 3 * WSTR) = make_float4(a0.w, a1.w, a2.w, a3.w);

        float4 b0 = *(const float4*)(wb + EE + 0 * (2 * EE));
        float4 b1 = *(const float4*)(wb + EE + 1 * (2 * EE));
        float4 b2 = *(const float4*)(wb + EE + 2 * (2 * EE));
        float4 b3 = *(const float4*)(wb + EE + 3 * (2 * EE));
        float* d2 = s_w2 + (kg * 4) * WSTR + csw;
        *(float4*)(d2 + 0 * WSTR) = make_float4(b0.x, b1.x, b2.x, b3.x);
        *(float4*)(d2 + 1 * WSTR) = make_float4(b0.y, b1.y, b2.y, b3.y);
        *(float4*)(d2 + 2 * WSTR) = make_float4(b0.z, b1.z, b2.z, b3.z);
        *(float4*)(d2 + 3 * WSTR) = make_float4(b0.w, b1.w, b2.w, b3.w);
    }

    __syncthreads();   // the only barrier

    // ---------------- sync-free mainloop over full K ------------------------
    unsigned long long acc1[2] = {};
    unsigned long long acc2[2] = {};

    const float* ax  = s_x + my * XSTR;
    const int    tx4 = tx * 4;

    #pragma unroll
    for (int ch = 0; ch < 16; ++ch) {
        #pragma unroll
        for (int k2 = 0; k2 < 16; ++k2) {
            const int k   = ch * 16 + k2;
            const int col = tx4 ^ (k & 28);          // compile-time per k
            const float* wr = s_w1 + k * WSTR + col;
            const ulonglong2 w1 = *(const ulonglong2*)wr;
            const ulonglong2 w2 = *(const ulonglong2*)(wr + SW_FLOATS);
            unsigned long long a = bcast2(ax[k]);

            fma2(acc1[0], a, w1.x); fma2(acc1[1], a, w1.y);
            fma2(acc2[0], a, w2.x); fma2(acc2[1], a, w2.y);
        }
    }

    // ---------------- epilogue ----------------------------------------------
    float4 bi = *(const float4*)&bias[f0 + tx4];
    float2 p0 = *(float2*)&acc1[0];
    float2 p1 = *(float2*)&acc1[1];
    float2 q0 = *(float2*)&acc2[0];
    float2 q1 = *(float2*)&acc2[1];

    const size_t o = (size_t)(m0 + my) * EE + f0 + tx4;
    *(float4*)&g_pi [o] = make_float4(p0.x, p0.y, p1.x, p1.y);
    *(float4*)&g_pjb[o] = make_float4(q0.x + bi.x, q0.y + bi.y,
                                      q1.x + bi.z, q1.y + bi.w);
}

// ---------------------------------------------------------------------------
// Kernel 2: per-batch broadcast add (proven body; b passed as arg).
// Grid per launch: (8 j-tiles, 64 i-tiles) = 512 blocks.
// ---------------------------------------------------------------------------
#define TI 4
#define TJ 32
#define E4 (EE / 4)

__global__ __launch_bounds__(256)
void add_kernel(float* __restrict__ out, int b)
{
    __shared__ float4 s_pj[TJ * E4];   // 32 KB

    const int i0  = blockIdx.y * TI;
    const int j0  = blockIdx.x * TJ;
    const int tid = threadIdx.x;
    const int e4  = tid & 63;
    const int jq  = tid >> 6;

    const float4* pi4 = (const float4*)g_pi  + (size_t)(b * SS + i0) * E4;
    const float4* pj4 = (const float4*)g_pjb + (size_t)(b * SS + j0) * E4;

    #pragma unroll
    for (int r = 0; r < 8; ++r)
        s_pj[tid + r * 256] = pj4[tid + r * 256];

    float4 pi_r[TI];
    #pragma unroll
    for (int i = 0; i < TI; ++i)
        pi_r[i] = pi4[i * E4 + e4];

    __syncthreads();

    float4* out4 = (float4*)out + ((size_t)(b * SS + i0) * SS + j0) * E4;

    #pragma unroll
    for (int jj = 0; jj < TJ / 4; ++jj) {
        int j = jq + jj * 4;
        float4 c = s_pj[j * E4 + e4];
        #pragma unroll
        for (int i = 0; i < TI; ++i) {
            float4 v = make_float4(pi_r[i].x + c.x, pi_r[i].y + c.y,
                                   pi_r[i].z + c.z, pi_r[i].w + c.w);
            __stcs(&out4[((size_t)i * SS + j) * E4 + e4], v);
        }
    }
}

// ---------------------------------------------------------------------------
// Launch: forked-stream graph. gemm_b on a high-priority non-blocking stream;
// add_b on the capture (legacy) stream waits on gemm_b's event. add_b0's
// 43us of DRAM-bound stores hides gemm_b1..b3 entirely.
// (Stream/event creation is host-side only — no device memory involved.
//  Objects are intentionally not destroyed: capture may still reference them;
//  kernel_launch is invoked only a handful of times.)
// ---------------------------------------------------------------------------
extern "C" void kernel_launch(void* const* d_in, const int* in_sizes, int n_in,
                              void* d_out, int out_size)
{
    const float* x    = (const float*)d_in[0];   // component_repr [4,256,256]
    const float* W    = (const float*)d_in[1];   // W [256,512]
    const float* bias = (const float*)d_in[2];   // b [256]
    float* out = (float*)d_out;                  // [4,256,256,256]

    cudaFuncSetAttribute(gemm_kernel,
                         cudaFuncAttributeMaxDynamicSharedMemorySize,
                         SMEM_BYTES);

    int prLo = 0, prHi = 0;
    cudaDeviceGetStreamPriorityRange(&prLo, &prHi);

    cudaStream_t gs;
    cudaStreamCreateWithPriority(&gs, cudaStreamNonBlocking, prHi);

    cudaEvent_t root, ev[BB];
    cudaEventCreateWithFlags(&root, cudaEventDisableTiming);
    for (int b = 0; b < BB; ++b)
        cudaEventCreateWithFlags(&ev[b], cudaEventDisableTiming);

    // fork gemm branch off the capture stream
    cudaEventRecord(root, 0);
    cudaStreamWaitEvent(gs, root, 0);

    for (int b = 0; b < BB; ++b) {
        gemm_kernel<<<dim3(SS / BM, EE / BN), 128, SMEM_BYTES, gs>>>(
            x, W, bias, b * SS);
        cudaEventRecord(ev[b], gs);
    }

    // adds on the capture stream, each gated on its batch's gemm
    for (int b = 0; b < BB; ++b) {
        cudaStreamWaitEvent(0, ev[b], 0);
        add_kernel<<<dim3(SS / TJ, SS / TI), 256>>>(out, b);
    }
}

// round 17
// speedup vs baseline: 1.2577x; 1.2577x over previous
#include <cuda_runtime.h>

// Problem shape (fixed by the dataset)
#define BB 4
#define SS 256
#define EE 256
#define MM (BB * SS)

// Scratch: pi[m,f] and (pj[m,f] + b[f]) — 1 MB each
__device__ float g_pi [MM * EE];
__device__ float g_pjb[MM * EE];

// ---------------------------------------------------------------------------
// Kernel 1: dual GEMM (R13 structure, best measured segment: 11.6us).
// 32x4 real tiles, grid padded to 37x4 = 148 CTAs (>=148 kills the low-grid
// I$ throttle on the >100KB unrolled body; extra CTAs return immediately).
//  - W in SMEM (k-major, XOR-swizzled columns: W[k][c] at col c ^ (k & 60)).
//  - x in REGISTERS (xr[16][4]); mainloop broadcasts via shfl.sync width=16.
//  - packed fma.rn.f32x2 accumulators; sync-free mainloop (one barrier).
// ---------------------------------------------------------------------------
#define BM 32
#define BN 64
#define MTILES (MM / BM)                 // 32 real m-tiles
#define GRIDX 37                         // padded: 37*4 = 148 CTAs

#define WSTR 68                          // W row stride (floats): 272B = 17*16
#define SW_FLOATS (EE * WSTR)            // 17408 floats per matrix
#define SMEM_BYTES (2 * SW_FLOATS * 4)   // 139,264 B

__device__ __forceinline__ void fma2(unsigned long long& acc,
                                     unsigned long long a,
                                     unsigned long long b)
{
    asm("fma.rn.f32x2 %0, %1, %2, %0;" : "+l"(acc) : "l"(a), "l"(b));
}

__device__ __forceinline__ unsigned long long bcast2(float a)
{
    unsigned long long r;
    asm("mov.b64 %0, {%1, %1};" : "=l"(r) : "r"(__float_as_int(a)));
    return r;
}

__global__ __launch_bounds__(128)
void gemm_kernel(const float* __restrict__ x,
                 const float* __restrict__ W,
                 const float* __restrict__ bias)
{
    if (blockIdx.x >= MTILES) return;    // grid padding (I$ throttle guard)

    extern __shared__ float sm[];
    float* s_w1 = sm;                    // [256 k][WSTR], swizzled cols
    float* s_w2 = sm + SW_FLOATS;

    const int m0  = blockIdx.x * BM;
    const int f0  = blockIdx.y * BN;
    const int tid = threadIdx.x;

    const int ty  = tid >> 4;    // 0..7: m-group (4 rows each); = shfl group
    const int tx  = tid & 15;    // 0..15: f-quad; also lane-within-group

    // ---------------- x -> registers (no smem) ------------------------------
    // xr[c][i] = x[m0 + ty*4 + i][c*16 + tx] ; half-warp reads 64B contiguous.
    float xr[16][4];
    #pragma unroll
    for (int c = 0; c < 16; ++c) {
        #pragma unroll
        for (int i = 0; i < 4; ++i)
            xr[c][i] = x[(size_t)(m0 + ty * 4 + i) * EE + c * 16 + tx];
    }

    // ---------------- W load: 4x4 register transpose -> [k][f], swizzled ----
    // element W[k][c] stored at float offset k*WSTR + (c ^ (k & 60)).
    #pragma unroll
    for (int i = 0; i < 8; ++i) {
        int t4 = tid + i * 128;               // 0..1023
        int fg = t4 >> 6;                     // f-group 0..15
        int kg = t4 & 63;                     // k-group 0..63
        const float* wb = W + (size_t)(f0 + fg * 4) * (2 * EE) + kg * 4;
        const int csw = (fg * 4) ^ ((kg & 15) << 2);

        float4 a0 = *(const float4*)(wb + 0 * (2 * EE));
        float4 a1 = *(const float4*)(wb + 1 * (2 * EE));
        float4 a2 = *(const float4*)(wb + 2 * (2 * EE));
        float4 a3 = *(const float4*)(wb + 3 * (2 * EE));
        float* d1 = s_w1 + (kg * 4) * WSTR + csw;
        *(float4*)(d1 + 0 * WSTR) = make_float4(a0.x, a1.x, a2.x, a3.x);
        *(float4*)(d1 + 1 * WSTR) = make_float4(a0.y, a1.y, a2.y, a3.y);
        *(float4*)(d1 + 2 * WSTR) = make_float4(a0.z, a1.z, a2.z, a3.z);
        *(float4*)(d1 + 3 * WSTR) = make_float4(a0.w, a1.w, a2.w, a3.w);

        float4 b0 = *(const float4*)(wb + EE + 0 * (2 * EE));
        float4 b1 = *(const float4*)(wb + EE + 1 * (2 * EE));
        float4 b2 = *(const float4*)(wb + EE + 2 * (2 * EE));
        float4 b3 = *(const float4*)(wb + EE + 3 * (2 * EE));
        float* d2 = s_w2 + (kg * 4) * WSTR + csw;
        *(float4*)(d2 + 0 * WSTR) = make_float4(b0.x, b1.x, b2.x, b3.x);
        *(float4*)(d2 + 1 * WSTR) = make_float4(b0.y, b1.y, b2.y, b3.y);
        *(float4*)(d2 + 2 * WSTR) = make_float4(b0.z, b1.z, b2.z, b3.z);
        *(float4*)(d2 + 3 * WSTR) = make_float4(b0.w, b1.w, b2.w, b3.w);
    }

    __syncthreads();   // the only barrier

    // ---------------- sync-free mainloop over full K ------------------------
    unsigned long long acc1[4][2] = {};
    unsigned long long acc2[4][2] = {};

    const int tx4 = tx * 4;

    #pragma unroll
    for (int ch = 0; ch < 16; ++ch) {
        const int chsw = (ch * 16) & 48;          // swizzle bits 4-5 of k
        const int txc  = tx4 ^ chsw;
        const float* wch = s_w1 + (ch * 16) * WSTR;

        #pragma unroll 4
        for (int k2 = 0; k2 < 16; ++k2) {
            const int colsw = txc ^ (k2 & 12);
            const float* wrow = wch + k2 * WSTR + colsw;
            const ulonglong2 w1 = *(const ulonglong2*)wrow;
            const ulonglong2 w2 = *(const ulonglong2*)(wrow + SW_FLOATS);

            float x0 = __shfl_sync(0xffffffffu, xr[ch][0], k2, 16);
            float x1 = __shfl_sync(0xffffffffu, xr[ch][1], k2, 16);
            float x2 = __shfl_sync(0xffffffffu, xr[ch][2], k2, 16);
            float x3 = __shfl_sync(0xffffffffu, xr[ch][3], k2, 16);
            unsigned long long a0 = bcast2(x0);
            unsigned long long a1 = bcast2(x1);
            unsigned long long a2 = bcast2(x2);
            unsigned long long a3 = bcast2(x3);

            fma2(acc1[0][0], a0, w1.x); fma2(acc1[0][1], a0, w1.y);
            fma2(acc1[1][0], a1, w1.x); fma2(acc1[1][1], a1, w1.y);
            fma2(acc1[2][0], a2, w1.x); fma2(acc1[2][1], a2, w1.y);
            fma2(acc1[3][0], a3, w1.x); fma2(acc1[3][1], a3, w1.y);

            fma2(acc2[0][0], a0, w2.x); fma2(acc2[0][1], a0, w2.y);
            fma2(acc2[1][0], a1, w2.x); fma2(acc2[1][1], a1, w2.y);
            fma2(acc2[2][0], a2, w2.x); fma2(acc2[2][1], a2, w2.y);
            fma2(acc2[3][0], a3, w2.x); fma2(acc2[3][1], a3, w2.y);
        }
    }

    // ---------------- epilogue ---------------------------------------------
    float4 bi = *(const float4*)&bias[f0 + tx4];

    #pragma unroll
    for (int i = 0; i < 4; ++i) {
        int m = m0 + ty * 4 + i;
        float2 p0 = *(float2*)&acc1[i][0];
        float2 p1 = *(float2*)&acc1[i][1];
        float2 q0 = *(float2*)&acc2[i][0];
        float2 q1 = *(float2*)&acc2[i][1];
        *(float4*)&g_pi [(size_t)m * EE + f0 + tx4] =
            make_float4(p0.x, p0.y, p1.x, p1.y);
        *(float4*)&g_pjb[(size_t)m * EE + f0 + tx4] =
            make_float4(q0.x + bi.x, q0.y + bi.y, q1.x + bi.z, q1.y + bi.w);
    }
}

// ---------------------------------------------------------------------------
// Kernel 2: broadcast add (frozen: 2048 blocks, ~43us — store-path ceiling).
// ---------------------------------------------------------------------------
#define TI 4
#define TJ 32
#define E4 (EE / 4)

__global__ __launch_bounds__(256)
void add_kernel(float* __restrict__ out)
{
    __shared__ float4 s_pj[TJ * E4];   // 32 KB

    const int b   = blockIdx.z;
    const int i0  = blockIdx.y * TI;
    const int j0  = blockIdx.x * TJ;
    const int tid = threadIdx.x;
    const int e4  = tid & 63;
    const int jq  = tid >> 6;

    const float4* pi4 = (const float4*)g_pi  + (size_t)(b * SS + i0) * E4;
    const float4* pj4 = (const float4*)g_pjb + (size_t)(b * SS + j0) * E4;

    #pragma unroll
    for (int r = 0; r < 8; ++r)
        s_pj[tid + r * 256] = pj4[tid + r * 256];

    float4 pi_r[TI];
    #pragma unroll
    for (int i = 0; i < TI; ++i)
        pi_r[i] = pi4[i * E4 + e4];

    __syncthreads();

    float4* out4 = (float4*)out + ((size_t)(b * SS + i0) * SS + j0) * E4;

    #pragma unroll
    for (int jj = 0; jj < TJ / 4; ++jj) {
        int j = jq + jj * 4;
        float4 c = s_pj[j * E4 + e4];
        #pragma unroll
        for (int i = 0; i < TI; ++i) {
            float4 v = make_float4(pi_r[i].x + c.x, pi_r[i].y + c.y,
                                   pi_r[i].z + c.z, pi_r[i].w + c.w);
            __stcs(&out4[((size_t)i * SS + j) * E4 + e4], v);
        }
    }
}

// ---------------------------------------------------------------------------
extern "C" void kernel_launch(void* const* d_in, const int* in_sizes, int n_in,
                              void* d_out, int out_size)
{
    const float* x    = (const float*)d_in[0];   // component_repr [4,256,256]
    const float* W    = (const float*)d_in[1];   // W [256,512]
    const float* bias = (const float*)d_in[2];   // b [256]
    float* out = (float*)d_out;                  // [4,256,256,256]

    // raise dynamic smem cap (idempotent attribute set, not an allocation)
    cudaFuncSetAttribute(gemm_kernel,
                         cudaFuncAttributeMaxDynamicSharedMemorySize,
                         SMEM_BYTES);

    dim3 gGemm(GRIDX, EE / BN);                  // 37 x 4 = 148 CTAs (32x4 real)
    gemm_kernel<<<gGemm, 128, SMEM_BYTES>>>(x, W, bias);

    dim3 gAdd(SS / TJ, SS / TI, BB);             // 8 x 64 x 4 = 2048 blocks
    add_kernel<<<gAdd, 256>>>(out);
}